// round 1
// baseline (speedup 1.0000x reference)
#include <cuda_runtime.h>
#include <cstdint>

#define B_  2
#define N_  16384
#define C_  64
#define S_  4096
#define K_  32

#define FEAT_OFF  (B_*S_*3)                 // 24576
#define SIDX_OFF  (FEAT_OFF + B_*128*S_)    // 24576 + 1048576

// ---------------- scratch (static __device__ per allocation rules) ----------------
__device__ float g_featT[B_ * N_ * C_];     // [B][N][C] transposed features (8.4MB)
__device__ int   g_idx[B_ * S_ * K_];       // ball-query neighbor indices

// ---------------- 1) transpose features [B,C,N] -> [B,N,C] ----------------
__global__ void k_transpose(const float* __restrict__ f) {
    __shared__ float t[32][33];
    int b  = blockIdx.z;
    int n0 = blockIdx.x * 32;
    int c0 = blockIdx.y * 32;
    int tx = threadIdx.x, ty = threadIdx.y;
#pragma unroll
    for (int i = 0; i < 32; i += 8)
        t[ty + i][tx] = f[(size_t)b * C_ * N_ + (size_t)(c0 + ty + i) * N_ + n0 + tx];
    __syncthreads();
#pragma unroll
    for (int i = 0; i < 32; i += 8)
        g_featT[(size_t)b * N_ * C_ + (size_t)(n0 + ty + i) * C_ + c0 + tx] = t[tx][ty + i];
}

// ---------------- 2) ball query: first 32 indices (ascending) with d2 < r2 ----------------
#define TP 2048
__global__ void __launch_bounds__(256) k_ballquery(const float* __restrict__ xyz) {
    __shared__ float sxyz[TP * 3];
    __shared__ float cen[8 * 3];
    int b    = blockIdx.y;
    int tid  = threadIdx.x;
    int warp = tid >> 5, lane = tid & 31;
    int s    = blockIdx.x * 8 + warp;

    if (tid < 24) cen[tid] = xyz[(size_t)b * N_ * 3 + (size_t)blockIdx.x * 8 * 3 + tid];
    __syncthreads();
    float cx = cen[warp * 3 + 0], cy = cen[warp * 3 + 1], cz = cen[warp * 3 + 2];
    float cn2 = cx * cx + cy * cy + cz * cz;
    const float r2 = (float)(0.4 * 0.4);   // match reference: f64 product rounded to f32

    int count  = 0;
    int firstn = 0;
    int outbase = (b * S_ + s) * K_;

    for (int t = 0; t < N_ / TP; t++) {
        int base = t * TP;
        for (int i = tid; i < TP * 3; i += 256)
            sxyz[i] = xyz[(size_t)b * N_ * 3 + (size_t)base * 3 + i];
        __syncthreads();

        if (count < K_) {
            for (int c = 0; c < TP / 32; c++) {
                int nl = c * 32 + lane;
                float x = sxyz[nl * 3 + 0];
                float y = sxyz[nl * 3 + 1];
                float z = sxyz[nl * 3 + 2];
                float pn2 = x * x + y * y + z * z;
                float dot = cx * x + cy * y + cz * z;
                float d2  = cn2 + pn2 - 2.0f * dot;   // reference formula
                bool  hit = d2 < r2;
                unsigned mask = __ballot_sync(0xffffffffu, hit);
                if (mask) {
                    if (count == 0) firstn = base + c * 32 + (__ffs(mask) - 1);
                    int slot = count + __popc(mask & ((1u << lane) - 1u));
                    if (hit && slot < K_) g_idx[outbase + slot] = base + nl;
                    count += __popc(mask);
                    if (count >= K_) break;
                }
            }
        }
        if (__syncthreads_and(count >= K_)) break;
    }
    // fill empty slots with first hit (0 if none)
    if (count < K_ && lane >= count) g_idx[outbase + lane] = firstn;
}

// ---------------- 3) fused gather + MLP(67->64->64->128) + maxpool ----------------
// Per CTA: 4 centroids = 128 rows. Register-tiled SGEMMs with weights in SMEM.
#define RSTR 132   // padded row stride for k-major activation buffers

// smem float offsets
#define O_W1   0        // 67*64  = 4288
#define O_W2   4288     // 64*64  = 4096
#define O_W3   8384     // 64*128 = 8192
#define O_B1   16576
#define O_B2   16640
#define O_B3   16704    // 128
#define O_G    16832    // 67*RSTR = 8844
#define O_H    25676    // 64*RSTR = 8448
#define O_RED  34124    // 512
#define O_CEN  34636    // 12
#define O_SIDX 34648    // 128 ints
#define SMEM_FLOATS (34648 + 128)
#define SMEM_BYTES  (SMEM_FLOATS * 4)

__global__ void __launch_bounds__(256, 1) k_mlp(
    const float* __restrict__ xyz,
    const float* __restrict__ W1, const float* __restrict__ b1,
    const float* __restrict__ W2, const float* __restrict__ b2,
    const float* __restrict__ W3, const float* __restrict__ b3,
    float* __restrict__ out)
{
    extern __shared__ float sm[];
    float* W1s = sm + O_W1;
    float* W2s = sm + O_W2;
    float* W3s = sm + O_W3;
    float* b1s = sm + O_B1;
    float* b2s = sm + O_B2;
    float* b3s = sm + O_B3;
    float* Gs  = sm + O_G;
    float* Hs  = sm + O_H;
    float* Red = sm + O_RED;
    float* cen = sm + O_CEN;
    int*   sidx = (int*)(sm + O_SIDX);

    int tid = threadIdx.x;
    int b   = blockIdx.y;
    int s0  = blockIdx.x * 4;

    for (int i = tid; i < 4288; i += 256) W1s[i] = W1[i];
    for (int i = tid; i < 4096; i += 256) W2s[i] = W2[i];
    for (int i = tid; i < 8192; i += 256) W3s[i] = W3[i];
    if (tid < 64)                  b1s[tid]       = b1[tid];
    else if (tid < 128)            b2s[tid - 64]  = b2[tid - 64];
    else                           b3s[tid - 128] = b3[tid - 128];
    if (tid < 128) sidx[tid] = g_idx[(b * S_ + s0) * K_ + tid];
    if (tid < 12)  cen[tid]  = xyz[((size_t)b * N_ + s0) * 3 + tid];
    for (int i = tid; i < 512; i += 256) Red[i] = 0.0f;
    __syncthreads();

    // gather: row r = (centroid r/32, sample r%32). 2 threads per row.
    {
        int r    = tid >> 1;
        int half = tid & 1;
        int n    = sidx[r];
        const float4* fp = (const float4*)(g_featT + ((size_t)b * N_ + n) * C_) + half * 8;
#pragma unroll
        for (int j = 0; j < 8; j++) {
            float4 v = fp[j];
            int cch = 3 + half * 32 + j * 4;
            Gs[(cch + 0) * RSTR + r] = v.x;
            Gs[(cch + 1) * RSTR + r] = v.y;
            Gs[(cch + 2) * RSTR + r] = v.z;
            Gs[(cch + 3) * RSTR + r] = v.w;
        }
        if (half == 0) {
            int g = r >> 5;
            float px = xyz[((size_t)b * N_ + n) * 3 + 0];
            float py = xyz[((size_t)b * N_ + n) * 3 + 1];
            float pz = xyz[((size_t)b * N_ + n) * 3 + 2];
            Gs[0 * RSTR + r] = px - cen[g * 3 + 0];
            Gs[1 * RSTR + r] = py - cen[g * 3 + 1];
            Gs[2 * RSTR + r] = pz - cen[g * 3 + 2];
        }
    }
    __syncthreads();

    int tr = tid >> 4;   // 16 row-threads, 8 rows each
    int tc = tid & 15;   // 16 col-threads

    // ---- layer 1: [128x67] @ [67x64] -> Hs (k-major) ----
    {
        float acc[8][4];
#pragma unroll
        for (int i = 0; i < 8; i++)
#pragma unroll
            for (int j = 0; j < 4; j++) acc[i][j] = 0.0f;
        for (int k = 0; k < 67; k++) {
            float4 a0 = *(const float4*)&Gs[k * RSTR + tr * 8];
            float4 a1 = *(const float4*)&Gs[k * RSTR + tr * 8 + 4];
            float4 bv = *(const float4*)&W1s[k * 64 + tc * 4];
            float a[8] = {a0.x, a0.y, a0.z, a0.w, a1.x, a1.y, a1.z, a1.w};
            float bb[4] = {bv.x, bv.y, bv.z, bv.w};
#pragma unroll
            for (int i = 0; i < 8; i++)
#pragma unroll
                for (int j = 0; j < 4; j++) acc[i][j] = fmaf(a[i], bb[j], acc[i][j]);
        }
#pragma unroll
        for (int j = 0; j < 4; j++) {
            int c = tc * 4 + j; float bb = b1s[c];
#pragma unroll
            for (int i = 0; i < 8; i++)
                Hs[c * RSTR + tr * 8 + i] = fmaxf(acc[i][j] + bb, 0.0f);
        }
    }
    __syncthreads();

    // ---- layer 2: [128x64] @ [64x64] -> Gs (reuse) ----
    {
        float acc[8][4];
#pragma unroll
        for (int i = 0; i < 8; i++)
#pragma unroll
            for (int j = 0; j < 4; j++) acc[i][j] = 0.0f;
        for (int k = 0; k < 64; k++) {
            float4 a0 = *(const float4*)&Hs[k * RSTR + tr * 8];
            float4 a1 = *(const float4*)&Hs[k * RSTR + tr * 8 + 4];
            float4 bv = *(const float4*)&W2s[k * 64 + tc * 4];
            float a[8] = {a0.x, a0.y, a0.z, a0.w, a1.x, a1.y, a1.z, a1.w};
            float bb[4] = {bv.x, bv.y, bv.z, bv.w};
#pragma unroll
            for (int i = 0; i < 8; i++)
#pragma unroll
                for (int j = 0; j < 4; j++) acc[i][j] = fmaf(a[i], bb[j], acc[i][j]);
        }
#pragma unroll
        for (int j = 0; j < 4; j++) {
            int c = tc * 4 + j; float bb = b2s[c];
#pragma unroll
            for (int i = 0; i < 8; i++)
                Gs[c * RSTR + tr * 8 + i] = fmaxf(acc[i][j] + bb, 0.0f);
        }
    }
    __syncthreads();

    // ---- layer 3: [128x64] @ [64x128], fused relu + maxpool over 32 rows ----
    {
        float acc[8][8];
#pragma unroll
        for (int i = 0; i < 8; i++)
#pragma unroll
            for (int j = 0; j < 8; j++) acc[i][j] = 0.0f;
        for (int k = 0; k < 64; k++) {
            float4 a0 = *(const float4*)&Gs[k * RSTR + tr * 8];
            float4 a1 = *(const float4*)&Gs[k * RSTR + tr * 8 + 4];
            float4 c0 = *(const float4*)&W3s[k * 128 + tc * 8];
            float4 c1 = *(const float4*)&W3s[k * 128 + tc * 8 + 4];
            float a[8]  = {a0.x, a0.y, a0.z, a0.w, a1.x, a1.y, a1.z, a1.w};
            float bb[8] = {c0.x, c0.y, c0.z, c0.w, c1.x, c1.y, c1.z, c1.w};
#pragma unroll
            for (int i = 0; i < 8; i++)
#pragma unroll
                for (int j = 0; j < 8; j++) acc[i][j] = fmaf(a[i], bb[j], acc[i][j]);
        }
        int g = tr >> 2;   // 8 rows of this thread live in one 32-row group
#pragma unroll
        for (int j = 0; j < 8; j++) {
            int c = tc * 8 + j; float bb = b3s[c];
            float m = 0.0f;    // relu folded into max-with-0
#pragma unroll
            for (int i = 0; i < 8; i++) m = fmaxf(m, acc[i][j] + bb);
            atomicMax((int*)&Red[g * 128 + c], __float_as_int(m));  // nonneg floats: int order == float order
        }
    }
    __syncthreads();

    for (int i = tid; i < 512; i += 256) {
        int g = i >> 7, c = i & 127;
        out[FEAT_OFF + ((size_t)b * 128 + c) * S_ + s0 + g] = Red[g * 128 + c];
    }
}

// ---------------- 4) new_xyz copy + samp_idx ----------------
__global__ void k_aux(const float* __restrict__ xyz, float* __restrict__ out) {
    int i = blockIdx.x * 256 + threadIdx.x;
    if (i < B_ * S_ * 3) {
        int b = i / (S_ * 3);
        int rem = i - b * (S_ * 3);
        out[i] = xyz[(size_t)b * N_ * 3 + rem];
    }
    if (i < B_ * S_) {
        out[SIDX_OFF + i] = (float)(i & (S_ - 1));
    }
}

// ---------------- launch ----------------
extern "C" void kernel_launch(void* const* d_in, const int* in_sizes, int n_in,
                              void* d_out, int out_size) {
    const float* xyz      = (const float*)d_in[0];
    const float* features = (const float*)d_in[1];
    const float* W1 = (const float*)d_in[2];
    const float* b1 = (const float*)d_in[3];
    const float* W2 = (const float*)d_in[4];
    const float* b2 = (const float*)d_in[5];
    const float* W3 = (const float*)d_in[6];
    const float* b3 = (const float*)d_in[7];
    float* out = (float*)d_out;

    cudaFuncSetAttribute(k_mlp, cudaFuncAttributeMaxDynamicSharedMemorySize, SMEM_BYTES);

    k_transpose<<<dim3(N_ / 32, C_ / 32, B_), dim3(32, 8)>>>(features);
    k_ballquery<<<dim3(S_ / 8, B_), 256>>>(xyz);
    k_mlp<<<dim3(S_ / 4, B_), 256, SMEM_BYTES>>>(xyz, W1, b1, W2, b2, W3, b3, out);
    k_aux<<<(B_ * S_ * 3 + 255) / 256, 256>>>(xyz, out);
}

// round 2
// speedup vs baseline: 1.0375x; 1.0375x over previous
#include <cuda_runtime.h>
#include <cstdint>

#define B_  2
#define N_  16384
#define C_  64
#define S_  4096
#define K_  32

#define FEAT_OFF  (B_*S_*3)                 // 24576
#define SIDX_OFF  (FEAT_OFF + B_*128*S_)    // 24576 + 1048576

// ---------------- scratch (static __device__ per allocation rules) ----------------
__device__ float g_featT[B_ * N_ * C_];     // [B][N][C] transposed features (8.4MB)
__device__ int   g_idx[B_ * S_ * K_];       // ball-query neighbor indices

// ---------------- packed f32x2 helpers (bit-exact dual fp32 FMA) ----------------
typedef unsigned long long u64t;
__device__ __forceinline__ u64t pk2(float x, float y) {
    u64t r; asm("mov.b64 %0, {%1, %2};" : "=l"(r) : "f"(x), "f"(y)); return r;
}
__device__ __forceinline__ void upk2(u64t v, float& x, float& y) {
    asm("mov.b64 {%0, %1}, %2;" : "=f"(x), "=f"(y) : "l"(v));
}
#define FMA2(acc, a, b) asm("fma.rn.f32x2 %0, %1, %2, %0;" : "+l"(acc) : "l"(a), "l"(b))

struct ull2 { u64t x, y; };

// ---------------- 1) transpose features [B,C,N] -> [B,N,C] ----------------
__global__ void k_transpose(const float* __restrict__ f) {
    __shared__ float t[32][33];
    int b  = blockIdx.z;
    int n0 = blockIdx.x * 32;
    int c0 = blockIdx.y * 32;
    int tx = threadIdx.x, ty = threadIdx.y;
#pragma unroll
    for (int i = 0; i < 32; i += 8)
        t[ty + i][tx] = f[(size_t)b * C_ * N_ + (size_t)(c0 + ty + i) * N_ + n0 + tx];
    __syncthreads();
#pragma unroll
    for (int i = 0; i < 32; i += 8)
        g_featT[(size_t)b * N_ * C_ + (size_t)(n0 + ty + i) * C_ + c0 + tx] = t[tx][ty + i];
}

// ---------------- 2) ball query: first 32 indices (ascending) with d2 < r2 ----------------
#define TP 2048
__global__ void __launch_bounds__(256) k_ballquery(const float* __restrict__ xyz) {
    __shared__ float sxyz[TP * 3];
    __shared__ float cen[8 * 3];
    int b    = blockIdx.y;
    int tid  = threadIdx.x;
    int warp = tid >> 5, lane = tid & 31;
    int s    = blockIdx.x * 8 + warp;

    if (tid < 24) cen[tid] = xyz[(size_t)b * N_ * 3 + (size_t)blockIdx.x * 8 * 3 + tid];
    __syncthreads();
    float cx = cen[warp * 3 + 0], cy = cen[warp * 3 + 1], cz = cen[warp * 3 + 2];
    float cn2 = cx * cx + cy * cy + cz * cz;
    const float r2 = (float)(0.4 * 0.4);   // match reference: f64 product rounded to f32

    int count  = 0;
    int firstn = 0;
    int outbase = (b * S_ + s) * K_;

    for (int t = 0; t < N_ / TP; t++) {
        int base = t * TP;
        for (int i = tid; i < TP * 3; i += 256)
            sxyz[i] = xyz[(size_t)b * N_ * 3 + (size_t)base * 3 + i];
        __syncthreads();

        if (count < K_) {
            for (int c = 0; c < TP / 32; c++) {
                int nl = c * 32 + lane;
                float x = sxyz[nl * 3 + 0];
                float y = sxyz[nl * 3 + 1];
                float z = sxyz[nl * 3 + 2];
                float pn2 = x * x + y * y + z * z;
                float dot = cx * x + cy * y + cz * z;
                float d2  = cn2 + pn2 - 2.0f * dot;   // reference formula
                bool  hit = d2 < r2;
                unsigned mask = __ballot_sync(0xffffffffu, hit);
                if (mask) {
                    if (count == 0) firstn = base + c * 32 + (__ffs(mask) - 1);
                    int slot = count + __popc(mask & ((1u << lane) - 1u));
                    if (hit && slot < K_) g_idx[outbase + slot] = base + nl;
                    count += __popc(mask);
                    if (count >= K_) break;
                }
            }
        }
        if (__syncthreads_and(count >= K_)) break;
    }
    // fill empty slots with first hit (0 if none)
    if (count < K_ && lane >= count) g_idx[outbase + lane] = firstn;
}

// ---------------- 3) fused gather + MLP(67->64->64->128) + maxpool ----------------
// Per CTA: 4 centroids = 128 rows. Register-tiled SGEMMs with weights in SMEM.
// Inner product loops use packed fma.rn.f32x2 (2 exact fp32 MACs / issue).
#define RSTR 132   // padded row stride for k-major activation buffers

// smem float offsets
#define O_W1   0        // 67*64  = 4288
#define O_W2   4288     // 64*64  = 4096
#define O_W3   8384     // 64*128 = 8192
#define O_B1   16576
#define O_B2   16640
#define O_B3   16704    // 128
#define O_G    16832    // 67*RSTR = 8844
#define O_H    25676    // 64*RSTR = 8448
#define O_RED  34124    // 512
#define O_CEN  34636    // 12
#define O_SIDX 34648    // 128 ints
#define SMEM_FLOATS (34648 + 128)
#define SMEM_BYTES  (SMEM_FLOATS * 4)

__global__ void __launch_bounds__(256, 1) k_mlp(
    const float* __restrict__ xyz,
    const float* __restrict__ W1, const float* __restrict__ b1,
    const float* __restrict__ W2, const float* __restrict__ b2,
    const float* __restrict__ W3, const float* __restrict__ b3,
    float* __restrict__ out)
{
    extern __shared__ float sm[];
    float* W1s = sm + O_W1;
    float* W2s = sm + O_W2;
    float* W3s = sm + O_W3;
    float* b1s = sm + O_B1;
    float* b2s = sm + O_B2;
    float* b3s = sm + O_B3;
    float* Gs  = sm + O_G;
    float* Hs  = sm + O_H;
    float* Red = sm + O_RED;
    float* cen = sm + O_CEN;
    int*   sidx = (int*)(sm + O_SIDX);

    int tid = threadIdx.x;
    int b   = blockIdx.y;
    int s0  = blockIdx.x * 4;

    for (int i = tid; i < 4288; i += 256) W1s[i] = W1[i];
    for (int i = tid; i < 4096; i += 256) W2s[i] = W2[i];
    for (int i = tid; i < 8192; i += 256) W3s[i] = W3[i];
    if (tid < 64)                  b1s[tid]       = b1[tid];
    else if (tid < 128)            b2s[tid - 64]  = b2[tid - 64];
    else                           b3s[tid - 128] = b3[tid - 128];
    if (tid < 128) sidx[tid] = g_idx[(b * S_ + s0) * K_ + tid];
    if (tid < 12)  cen[tid]  = xyz[((size_t)b * N_ + s0) * 3 + tid];
    for (int i = tid; i < 512; i += 256) Red[i] = 0.0f;
    __syncthreads();

    // gather: row r = (centroid r/32, sample r%32). 2 threads per row.
    {
        int r    = tid >> 1;
        int half = tid & 1;
        int n    = sidx[r];
        const float4* fp = (const float4*)(g_featT + ((size_t)b * N_ + n) * C_) + half * 8;
#pragma unroll
        for (int j = 0; j < 8; j++) {
            float4 v = fp[j];
            int cch = 3 + half * 32 + j * 4;
            Gs[(cch + 0) * RSTR + r] = v.x;
            Gs[(cch + 1) * RSTR + r] = v.y;
            Gs[(cch + 2) * RSTR + r] = v.z;
            Gs[(cch + 3) * RSTR + r] = v.w;
        }
        if (half == 0) {
            int g = r >> 5;
            float px = xyz[((size_t)b * N_ + n) * 3 + 0];
            float py = xyz[((size_t)b * N_ + n) * 3 + 1];
            float pz = xyz[((size_t)b * N_ + n) * 3 + 2];
            Gs[0 * RSTR + r] = px - cen[g * 3 + 0];
            Gs[1 * RSTR + r] = py - cen[g * 3 + 1];
            Gs[2 * RSTR + r] = pz - cen[g * 3 + 2];
        }
    }
    __syncthreads();

    int tr = tid >> 4;   // 16 row-threads, 8 rows each
    int tc = tid & 15;   // 16 col-threads
    int arow = tr * 8;

    // ---- layer 1: [128x67] @ [67x64] -> Hs (k-major), packed i-pairs ----
    {
        u64t acc[4][4];
#pragma unroll
        for (int i = 0; i < 4; i++)
#pragma unroll
            for (int j = 0; j < 4; j++) acc[i][j] = 0ull;
#pragma unroll 2
        for (int k = 0; k < 67; k++) {
            ull2 av0 = *(const ull2*)&Gs[k * RSTR + arow];
            ull2 av1 = *(const ull2*)&Gs[k * RSTR + arow + 4];
            u64t ap[4] = {av0.x, av0.y, av1.x, av1.y};
            float4 bv = *(const float4*)&W1s[k * 64 + tc * 4];
            u64t bp[4] = {pk2(bv.x, bv.x), pk2(bv.y, bv.y), pk2(bv.z, bv.z), pk2(bv.w, bv.w)};
#pragma unroll
            for (int i = 0; i < 4; i++)
#pragma unroll
                for (int j = 0; j < 4; j++) FMA2(acc[i][j], ap[i], bp[j]);
        }
#pragma unroll
        for (int j = 0; j < 4; j++) {
            int c = tc * 4 + j; float bb = b1s[c];
#pragma unroll
            for (int i = 0; i < 4; i++) {
                float x, y; upk2(acc[i][j], x, y);
                float2 st = make_float2(fmaxf(x + bb, 0.0f), fmaxf(y + bb, 0.0f));
                *(float2*)&Hs[c * RSTR + arow + 2 * i] = st;
            }
        }
    }
    __syncthreads();

    // ---- layer 2: [128x64] @ [64x64] -> Gs (reuse) ----
    {
        u64t acc[4][4];
#pragma unroll
        for (int i = 0; i < 4; i++)
#pragma unroll
            for (int j = 0; j < 4; j++) acc[i][j] = 0ull;
#pragma unroll 2
        for (int k = 0; k < 64; k++) {
            ull2 av0 = *(const ull2*)&Hs[k * RSTR + arow];
            ull2 av1 = *(const ull2*)&Hs[k * RSTR + arow + 4];
            u64t ap[4] = {av0.x, av0.y, av1.x, av1.y};
            float4 bv = *(const float4*)&W2s[k * 64 + tc * 4];
            u64t bp[4] = {pk2(bv.x, bv.x), pk2(bv.y, bv.y), pk2(bv.z, bv.z), pk2(bv.w, bv.w)};
#pragma unroll
            for (int i = 0; i < 4; i++)
#pragma unroll
                for (int j = 0; j < 4; j++) FMA2(acc[i][j], ap[i], bp[j]);
        }
#pragma unroll
        for (int j = 0; j < 4; j++) {
            int c = tc * 4 + j; float bb = b2s[c];
#pragma unroll
            for (int i = 0; i < 4; i++) {
                float x, y; upk2(acc[i][j], x, y);
                float2 st = make_float2(fmaxf(x + bb, 0.0f), fmaxf(y + bb, 0.0f));
                *(float2*)&Gs[c * RSTR + arow + 2 * i] = st;
            }
        }
    }
    __syncthreads();

    // ---- layer 3: [128x64] @ [64x128], fused relu + maxpool over 32 rows ----
    {
        u64t acc[4][8];
#pragma unroll
        for (int i = 0; i < 4; i++)
#pragma unroll
            for (int j = 0; j < 8; j++) acc[i][j] = 0ull;
#pragma unroll 2
        for (int k = 0; k < 64; k++) {
            ull2 av0 = *(const ull2*)&Gs[k * RSTR + arow];
            ull2 av1 = *(const ull2*)&Gs[k * RSTR + arow + 4];
            u64t ap[4] = {av0.x, av0.y, av1.x, av1.y};
            float4 c0 = *(const float4*)&W3s[k * 128 + tc * 8];
            float4 c1 = *(const float4*)&W3s[k * 128 + tc * 8 + 4];
            u64t bp[8] = {pk2(c0.x, c0.x), pk2(c0.y, c0.y), pk2(c0.z, c0.z), pk2(c0.w, c0.w),
                          pk2(c1.x, c1.x), pk2(c1.y, c1.y), pk2(c1.z, c1.z), pk2(c1.w, c1.w)};
#pragma unroll
            for (int i = 0; i < 4; i++)
#pragma unroll
                for (int j = 0; j < 8; j++) FMA2(acc[i][j], ap[i], bp[j]);
        }
        int g = tr >> 2;   // this thread's 8 rows live in one 32-row group
#pragma unroll
        for (int j = 0; j < 8; j++) {
            int c = tc * 8 + j; float bb = b3s[c];
            float m = 0.0f;    // relu folded into max-with-0
#pragma unroll
            for (int i = 0; i < 4; i++) {
                float x, y; upk2(acc[i][j], x, y);
                m = fmaxf(m, fmaxf(x + bb, y + bb));
            }
            atomicMax((int*)&Red[g * 128 + c], __float_as_int(m));  // nonneg floats: int order == float order
        }
    }
    __syncthreads();

    for (int i = tid; i < 512; i += 256) {
        int g = i >> 7, c = i & 127;
        out[FEAT_OFF + ((size_t)b * 128 + c) * S_ + s0 + g] = Red[g * 128 + c];
    }
}

// ---------------- 4) new_xyz copy + samp_idx ----------------
__global__ void k_aux(const float* __restrict__ xyz, float* __restrict__ out) {
    int i = blockIdx.x * 256 + threadIdx.x;
    if (i < B_ * S_ * 3) {
        int b = i / (S_ * 3);
        int rem = i - b * (S_ * 3);
        out[i] = xyz[(size_t)b * N_ * 3 + rem];
    }
    if (i < B_ * S_) {
        out[SIDX_OFF + i] = (float)(i & (S_ - 1));
    }
}

// ---------------- launch ----------------
extern "C" void kernel_launch(void* const* d_in, const int* in_sizes, int n_in,
                              void* d_out, int out_size) {
    const float* xyz      = (const float*)d_in[0];
    const float* features = (const float*)d_in[1];
    const float* W1 = (const float*)d_in[2];
    const float* b1 = (const float*)d_in[3];
    const float* W2 = (const float*)d_in[4];
    const float* b2 = (const float*)d_in[5];
    const float* W3 = (const float*)d_in[6];
    const float* b3 = (const float*)d_in[7];
    float* out = (float*)d_out;

    cudaFuncSetAttribute(k_mlp, cudaFuncAttributeMaxDynamicSharedMemorySize, SMEM_BYTES);

    k_transpose<<<dim3(N_ / 32, C_ / 32, B_), dim3(32, 8)>>>(features);
    k_ballquery<<<dim3(S_ / 8, B_), 256>>>(xyz);
    k_mlp<<<dim3(S_ / 4, B_), 256, SMEM_BYTES>>>(xyz, W1, b1, W2, b2, W3, b3, out);
    k_aux<<<(B_ * S_ * 3 + 255) / 256, 256>>>(xyz, out);
}